// round 2
// baseline (speedup 1.0000x reference)
#include <cuda_runtime.h>
#include <math.h>

#define Bb   2
#define Ll   1000
#define Dd   288
#define Hh   8
#define DIMv 36
#define DFFv 576
#define KSv  250
#define NQv  250
#define EPSv 1e-5f
#define NROW (Bb*Ll)        // 2000

// ------------------------- device scratch (no allocs) -------------------------
__device__ __align__(16) float g_Wqt[Dd*Dd];
__device__ __align__(16) float g_Wkt[Dd*Dd];
__device__ __align__(16) float g_Wvt[Dd*Dd];
__device__ __align__(16) float g_W1t[Dd*DFFv];   // [288][576]
__device__ __align__(16) float g_W2t[DFFv*Dd];   // [576][288]
__device__ __align__(16) float g_q[Bb*Hh*Ll*DIMv];
__device__ __align__(16) float g_k[Bb*Hh*Ll*DIMv];
__device__ __align__(16) float g_v[Bb*Hh*Ll*DIMv];
__device__ __align__(16) float g_measure[Bb*Hh*Ll];
__device__             int   g_idxq[Bb*Hh*NQv];
__device__             int   g_cnt[Bb*Hh];
__device__ __align__(16) float g_vmean[Bb*Hh*DIMv];
__device__ __align__(16) float g_attn[Bb*Ll*Dd];
__device__ __align__(16) float g_h1[Bb*Ll*Dd];
__device__ __align__(16) float g_f1[Bb*Ll*DFFv];
__device__ __align__(16) float g_h2[Bb*Ll*Dd];

// ------------------------- helpers -------------------------
__device__ __forceinline__ float warp_sum(float v) {
    #pragma unroll
    for (int o = 16; o; o >>= 1) v += __shfl_xor_sync(0xffffffffu, v, o);
    return v;
}
__device__ __forceinline__ float warp_max(float v) {
    #pragma unroll
    for (int o = 16; o; o >>= 1) v = fmaxf(v, __shfl_xor_sync(0xffffffffu, v, o));
    return v;
}
__device__ __forceinline__ float gelu_exact(float a) {
    return 0.5f * a * (1.0f + erff(a * 0.70710678118654752f));
}

// ------------------------- kernels -------------------------
__global__ void k_reset() {
    if (threadIdx.x < Bb*Hh) g_cnt[threadIdx.x] = 0;
}

// dst[c*rows + r] = src[r*cols + c]
__global__ void k_transpose(const float* __restrict__ src, float* __restrict__ dst,
                            int rows, int cols) {
    int i = blockIdx.x * blockDim.x + threadIdx.x;
    if (i < rows * cols) {
        int r = i / cols, c = i % cols;
        dst[c * rows + r] = src[i];
    }
}

// QKV projection, 8 rows per block, 288 threads (one output column each).
__global__ void __launch_bounds__(Dd) k_qkv(const float* __restrict__ x,
                                            const float* __restrict__ bq,
                                            const float* __restrict__ bk,
                                            const float* __restrict__ bv) {
    __shared__ float xs[8 * Dd];
    int base = blockIdx.x * 8;
    int j = threadIdx.x;
    for (int i = j; i < 8 * Dd; i += Dd) xs[i] = x[base * Dd + i];
    __syncthreads();

    float aq[8], ak[8], av[8];
    float bqv = bq[j], bkv = bk[j], bvv = bv[j];
    #pragma unroll
    for (int r = 0; r < 8; r++) { aq[r] = bqv; ak[r] = bkv; av[r] = bvv; }

    for (int i = 0; i < Dd; i++) {
        float wq = g_Wqt[i * Dd + j];
        float wk = g_Wkt[i * Dd + j];
        float wv = g_Wvt[i * Dd + j];
        #pragma unroll
        for (int r = 0; r < 8; r++) {
            float xi = xs[r * Dd + i];
            aq[r] = fmaf(xi, wq, aq[r]);
            ak[r] = fmaf(xi, wk, ak[r]);
            av[r] = fmaf(xi, wv, av[r]);
        }
    }
    int h = j / DIMv, dd = j % DIMv;
    #pragma unroll
    for (int r = 0; r < 8; r++) {
        int row = base + r;
        int b = row / Ll, l = row % Ll;
        int o = ((b * Hh + h) * Ll + l) * DIMv + dd;
        g_q[o] = aq[r]; g_k[o] = ak[r]; g_v[o] = av[r];
    }
}

// Sampled scores -> sparsity measure.  grid = 16 bh * 8 chunks, 512 threads,
// full per-head K tile (144 KB) in dynamic SMEM.
__global__ void __launch_bounds__(512) k_measure(const int* __restrict__ index_key) {
    extern __shared__ __align__(16) float ks[];   // [1000][36]
    int bh = blockIdx.x >> 3;
    int chunk = blockIdx.x & 7;
    const float4* kb4 = (const float4*)(g_k + bh * Ll * DIMv);
    for (int i = threadIdx.x; i < Ll * DIMv / 4; i += 512)
        ((float4*)ks)[i] = kb4[i];
    __syncthreads();

    int warp = threadIdx.x >> 5, lane = threadIdx.x & 31;
    const float* qb = g_q + bh * Ll * DIMv;
    int q0 = chunk * 125;
    for (int ql = q0 + warp; ql < q0 + 125; ql += 16) {
        float qreg[DIMv];
        #pragma unroll
        for (int d = 0; d < DIMv; d++) qreg[d] = qb[ql * DIMv + d];
        float mx = -1e30f, sm = 0.0f;
        for (int s = lane; s < KSv; s += 32) {
            int idx = index_key[ql * KSv + s];
            const float* kr = ks + idx * DIMv;
            float acc = 0.0f;
            #pragma unroll
            for (int d = 0; d < DIMv; d += 4) {
                float4 kv = *(const float4*)(kr + d);
                acc = fmaf(qreg[d + 0], kv.x, acc);
                acc = fmaf(qreg[d + 1], kv.y, acc);
                acc = fmaf(qreg[d + 2], kv.z, acc);
                acc = fmaf(qreg[d + 3], kv.w, acc);
            }
            mx = fmaxf(mx, acc);
            sm += acc;
        }
        mx = warp_max(mx);
        sm = warp_sum(sm);
        if (lane == 0) g_measure[bh * Ll + ql] = mx - sm * (1.0f / (float)Ll);
    }
}

// Exact top-NQ per (b,h) via rank counting (matches jax top_k tie semantics).
// grid = 16 bh * 8 chunks, 128 threads (125 active).
__global__ void k_topk() {
    __shared__ float ms[Ll];
    int bh = blockIdx.x >> 3, chunk = blockIdx.x & 7;
    for (int i = threadIdx.x; i < Ll; i += 128) ms[i] = g_measure[bh * Ll + i];
    __syncthreads();
    int t = chunk * 125 + threadIdx.x;
    if (threadIdx.x < 125) {
        float v = ms[t];
        int cnt = 0;
        #pragma unroll 4
        for (int jj = 0; jj < Ll; jj++) {
            float u = ms[jj];
            cnt += (u > v) || (u == v && jj < t);
        }
        if (cnt < NQv) {
            int slot = atomicAdd(&g_cnt[bh], 1);
            g_idxq[bh * NQv + slot] = t;
        }
    }
}

// mean of V over L per (b,h).  grid 16, block 288 = 8 sub * 36 dims.
__global__ void k_vmean() {
    __shared__ float red[288];
    int bh = blockIdx.x, tid = threadIdx.x;
    int sub = tid / DIMv, dd = tid % DIMv;
    float s = 0.0f;
    for (int l = sub; l < Ll; l += 8) s += g_v[(bh * Ll + l) * DIMv + dd];
    red[tid] = s;
    __syncthreads();
    if (sub == 0) {
        float tot = 0.0f;
        #pragma unroll
        for (int r = 0; r < 8; r++) tot += red[r * DIMv + dd];
        g_vmean[bh * DIMv + dd] = tot * (1.0f / (float)Ll);
    }
}

// broadcast vmean into the attention output (lazy queries).  grid 2000, 288 thr.
__global__ void k_init_attn() {
    int row = blockIdx.x, j = threadIdx.x;
    int b = row / Ll;
    int h = j / DIMv, dd = j % DIMv;
    g_attn[row * Dd + j] = g_vmean[(b * Hh + h) * DIMv + dd];
}

// dense attention for selected queries.  grid = 16*250, 256 threads per query.
__global__ void __launch_bounds__(256) k_attn() {
    __shared__ float sc[Ll];
    __shared__ float red8[8];
    __shared__ float bcast;
    __shared__ float outred[8][DIMv];
    int bh = blockIdx.x / NQv, qslot = blockIdx.x % NQv;
    int qi = g_idxq[bh * NQv + qslot];
    int tid = threadIdx.x, warp = tid >> 5, lane = tid & 31;

    const float* qrow = g_q + (bh * Ll + qi) * DIMv;
    float qreg[DIMv];
    #pragma unroll
    for (int d = 0; d < DIMv; d++) qreg[d] = qrow[d] * (1.0f / 6.0f);  // 1/sqrt(36)

    const float* kb = g_k + bh * Ll * DIMv;
    float lmax = -1e30f;
    for (int kk = tid; kk < Ll; kk += 256) {
        const float4* kr = (const float4*)(kb + kk * DIMv);
        float acc = 0.0f;
        #pragma unroll
        for (int i = 0; i < 9; i++) {
            float4 kv = kr[i];
            acc = fmaf(qreg[4*i+0], kv.x, acc);
            acc = fmaf(qreg[4*i+1], kv.y, acc);
            acc = fmaf(qreg[4*i+2], kv.z, acc);
            acc = fmaf(qreg[4*i+3], kv.w, acc);
        }
        sc[kk] = acc;
        lmax = fmaxf(lmax, acc);
    }
    lmax = warp_max(lmax);
    if (lane == 0) red8[warp] = lmax;
    __syncthreads();
    if (tid == 0) {
        float m = red8[0];
        #pragma unroll
        for (int w = 1; w < 8; w++) m = fmaxf(m, red8[w]);
        bcast = m;
    }
    __syncthreads();
    float mx = bcast;
    __syncthreads();

    float lsum = 0.0f;
    for (int kk = tid; kk < Ll; kk += 256) {
        float e = expf(sc[kk] - mx);
        sc[kk] = e;
        lsum += e;
    }
    lsum = warp_sum(lsum);
    if (lane == 0) red8[warp] = lsum;
    __syncthreads();
    if (tid == 0) {
        float s = 0.0f;
        #pragma unroll
        for (int w = 0; w < 8; w++) s += red8[w];
        bcast = s;
    }
    __syncthreads();
    float inv = 1.0f / bcast;
    __syncthreads();

    // out = (sum_k e_k * v_k) * inv
    float va[DIMv];
    #pragma unroll
    for (int d = 0; d < DIMv; d++) va[d] = 0.0f;
    const float* vb = g_v + bh * Ll * DIMv;
    for (int kk = tid; kk < Ll; kk += 256) {
        float p = sc[kk];
        const float4* vr = (const float4*)(vb + kk * DIMv);
        #pragma unroll
        for (int i = 0; i < 9; i++) {
            float4 vv = vr[i];
            va[4*i+0] = fmaf(p, vv.x, va[4*i+0]);
            va[4*i+1] = fmaf(p, vv.y, va[4*i+1]);
            va[4*i+2] = fmaf(p, vv.z, va[4*i+2]);
            va[4*i+3] = fmaf(p, vv.w, va[4*i+3]);
        }
    }
    #pragma unroll
    for (int d = 0; d < DIMv; d++) {
        #pragma unroll
        for (int o = 16; o; o >>= 1) va[d] += __shfl_xor_sync(0xffffffffu, va[d], o);
    }
    if (lane == 0) {
        #pragma unroll
        for (int d = 0; d < DIMv; d++) outred[warp][d] = va[d];
    }
    __syncthreads();
    if (tid < DIMv) {
        float tot = 0.0f;
        #pragma unroll
        for (int w = 0; w < 8; w++) tot += outred[w][tid];
        int b = bh / Hh, h = bh % Hh;
        g_attn[(b * Ll + qi) * Dd + h * DIMv + tid] = tot * inv;
    }
}

// residual + layernorm: out = LN(src_a + src_b).  grid 2000, 288 threads.
__global__ void __launch_bounds__(Dd) k_res_ln(const float* __restrict__ a,
                                              const float* __restrict__ bsrc,
                                              const float* __restrict__ gamma,
                                              const float* __restrict__ beta,
                                              float* __restrict__ out) {
    __shared__ float red9[9];
    __shared__ float bval;
    int row = blockIdx.x, j = threadIdx.x;
    int warp = j >> 5, lane = j & 31;
    float v = a[row * Dd + j] + bsrc[row * Dd + j];

    float s = warp_sum(v);
    if (lane == 0) red9[warp] = s;
    __syncthreads();
    if (j == 0) {
        float t = 0.0f;
        #pragma unroll
        for (int w = 0; w < 9; w++) t += red9[w];
        bval = t;
    }
    __syncthreads();
    float mu = bval * (1.0f / (float)Dd);
    float c = v - mu;
    __syncthreads();
    float s2 = warp_sum(c * c);
    if (lane == 0) red9[warp] = s2;
    __syncthreads();
    if (j == 0) {
        float t = 0.0f;
        #pragma unroll
        for (int w = 0; w < 9; w++) t += red9[w];
        bval = t;
    }
    __syncthreads();
    float var = bval * (1.0f / (float)Dd);
    out[row * Dd + j] = c * rsqrtf(var + EPSv) * gamma[j] + beta[j];
}

// FFN layer 1: f = gelu(h1 @ W1^T + b1).  8 rows/block, 576 threads.
__global__ void __launch_bounds__(DFFv) k_ffn1(const float* __restrict__ b1) {
    __shared__ float hs[8 * Dd];
    int base = blockIdx.x * 8;
    int j = threadIdx.x;
    for (int i = j; i < 8 * Dd; i += DFFv) hs[i] = g_h1[base * Dd + i];
    __syncthreads();
    float acc[8];
    float bj = b1[j];
    #pragma unroll
    for (int r = 0; r < 8; r++) acc[r] = bj;
    for (int i = 0; i < Dd; i++) {
        float w = g_W1t[i * DFFv + j];
        #pragma unroll
        for (int r = 0; r < 8; r++) acc[r] = fmaf(hs[r * Dd + i], w, acc[r]);
    }
    #pragma unroll
    for (int r = 0; r < 8; r++)
        g_f1[(base + r) * DFFv + j] = gelu_exact(acc[r]);
}

// FFN layer 2 + residual: h2 = gelu(f @ W2^T + b2) + h1.  8 rows/block, 288 thr.
__global__ void __launch_bounds__(Dd) k_ffn2(const float* __restrict__ b2) {
    __shared__ float fs[8 * DFFv];
    int base = blockIdx.x * 8;
    int j = threadIdx.x;
    for (int i = j; i < 8 * DFFv; i += Dd) fs[i] = g_f1[base * DFFv + i];
    __syncthreads();
    float acc[8];
    float bj = b2[j];
    #pragma unroll
    for (int r = 0; r < 8; r++) acc[r] = bj;
    for (int i = 0; i < DFFv; i++) {
        float w = g_W2t[i * Dd + j];
        #pragma unroll
        for (int r = 0; r < 8; r++) acc[r] = fmaf(fs[r * DFFv + i], w, acc[r]);
    }
    #pragma unroll
    for (int r = 0; r < 8; r++) {
        int row = base + r;
        g_h2[row * Dd + j] = gelu_exact(acc[r]) + g_h1[row * Dd + j];
    }
}

// zero-add layernorm wrapper buffer (for LN over a single tensor we pass b=0):
__device__ __align__(16) float g_zero[Bb*Ll*Dd];
__global__ void k_zero() {
    int i = blockIdx.x * blockDim.x + threadIdx.x;
    if (i < Bb*Ll*Dd) g_zero[i] = 0.0f;
}

// ------------------------- launch -------------------------
extern "C" void kernel_launch(void* const* d_in, const int* in_sizes, int n_in,
                              void* d_out, int out_size) {
    const float* x     = (const float*)d_in[0];
    const int*   ikey  = (const int*)  d_in[1];
    const float* Wq    = (const float*)d_in[2];
    const float* bq    = (const float*)d_in[3];
    const float* Wk    = (const float*)d_in[4];
    const float* bk    = (const float*)d_in[5];
    const float* Wv    = (const float*)d_in[6];
    const float* bv    = (const float*)d_in[7];
    const float* W1    = (const float*)d_in[8];
    const float* b1    = (const float*)d_in[9];
    const float* W2    = (const float*)d_in[10];
    const float* b2    = (const float*)d_in[11];
    const float* ln1g  = (const float*)d_in[12];
    const float* ln1b  = (const float*)d_in[13];
    const float* ln2g  = (const float*)d_in[14];
    const float* ln2b  = (const float*)d_in[15];
    float* out = (float*)d_out;

    float *Wqt, *Wkt, *Wvt, *W1t, *W2t, *h1, *h2, *attnp, *zerop;
    cudaGetSymbolAddress((void**)&Wqt, g_Wqt);
    cudaGetSymbolAddress((void**)&Wkt, g_Wkt);
    cudaGetSymbolAddress((void**)&Wvt, g_Wvt);
    cudaGetSymbolAddress((void**)&W1t, g_W1t);
    cudaGetSymbolAddress((void**)&W2t, g_W2t);
    cudaGetSymbolAddress((void**)&h1,  g_h1);
    cudaGetSymbolAddress((void**)&h2,  g_h2);
    cudaGetSymbolAddress((void**)&attnp, g_attn);
    cudaGetSymbolAddress((void**)&zerop, g_zero);

    static const int MEAS_SMEM = Ll * DIMv * sizeof(float);  // 144000 B
    cudaFuncSetAttribute(k_measure, cudaFuncAttributeMaxDynamicSharedMemorySize, MEAS_SMEM);

    k_reset<<<1, 32>>>();
    k_transpose<<<(Dd*Dd + 255)/256, 256>>>(Wq, Wqt, Dd, Dd);
    k_transpose<<<(Dd*Dd + 255)/256, 256>>>(Wk, Wkt, Dd, Dd);
    k_transpose<<<(Dd*Dd + 255)/256, 256>>>(Wv, Wvt, Dd, Dd);
    k_transpose<<<(DFFv*Dd + 255)/256, 256>>>(W1, W1t, DFFv, Dd);
    k_transpose<<<(Dd*DFFv + 255)/256, 256>>>(W2, W2t, Dd, DFFv);

    k_qkv<<<NROW/8, Dd>>>(x, bq, bk, bv);
    k_measure<<<Bb*Hh*8, 512, MEAS_SMEM>>>(ikey);
    k_topk<<<Bb*Hh*8, 128>>>();
    k_vmean<<<Bb*Hh, 288>>>();
    k_init_attn<<<NROW, Dd>>>();
    k_attn<<<Bb*Hh*NQv, 256>>>();
    // h1 = LN1(x + attn)
    k_res_ln<<<NROW, Dd>>>(x, attnp, ln1g, ln1b, h1);
    k_ffn1<<<NROW/8, DFFv>>>(b1);
    k_ffn2<<<NROW/8, Dd>>>(b2);
    // out = LN2(h2 + 0)  (residual already folded into h2)
    k_zero<<<(Bb*Ll*Dd + 255)/256, 256>>>();
    k_res_ln<<<NROW, Dd>>>(h2, zerop, ln2g, ln2b, out);
}